// round 1
// baseline (speedup 1.0000x reference)
#include <cuda_runtime.h>

// Problem dims (fixed for this problem instance)
constexpr int N_IN  = 32;
constexpr int H_IN  = 56;
constexpr int W_IN  = 56;
constexpr int C_IN  = 256;
constexpr int KH    = 3;
constexpr int KW    = 3;
constexpr int OC    = 256;
constexpr int OH    = 54;   // VALID: 56-3+1
constexpr int OW    = 54;

constexpr int M_TOTAL = N_IN * OH * OW;   // 93312
constexpr int K_TOTAL = KH * KW * C_IN;   // 2304

constexpr float SPARSE_TH = 0.01f;

// GEMM tiling
constexpr int BM = 128;
constexpr int BN = 128;
constexpr int BK = 32;
constexpr int AS_STRIDE = BK + 4;  // 36 floats/row: 144B, 16B-aligned, kills LDS bank conflicts

// Packed/thresholded weight: B[k][o], k = (kh*3+kw)*256 + ic  (2.36 MB scratch)
__device__ float g_B[K_TOTAL * OC];

// ---------------------------------------------------------------------------
// Prep: weight OIHW -> thresholded B[k][o]
// ---------------------------------------------------------------------------
__global__ void prep_weight_kernel(const float* __restrict__ w) {
    int k  = blockIdx.x;        // 0..2303
    int o  = threadIdx.x;       // 0..255
    int p  = k >> 8;            // (kh*3+kw)
    int ic = k & 255;
    int kh = p / 3;
    int kw = p - kh * 3;
    // OIHW strides: o:2304, i:9, kh:3, kw:1
    float v = w[o * (C_IN * KH * KW) + ic * (KH * KW) + kh * KW + kw];
    if (fabsf(v) < SPARSE_TH) v = 0.0f;
    g_B[k * OC + o] = v;
}

// ---------------------------------------------------------------------------
// Main: implicit-GEMM conv, fp32, 128x128x32 tiles, 8x8 per-thread micro-tile
// ---------------------------------------------------------------------------
__global__ __launch_bounds__(256, 2)
void conv_gemm_kernel(const float* __restrict__ x,
                      const float* __restrict__ bias,
                      float* __restrict__ out) {
    __shared__ float As[BM][AS_STRIDE];  // [m][k], 18 KB
    __shared__ float Bs[BK][BN];         // [k][o], 16 KB

    const int tid = threadIdx.x;
    const int bm  = blockIdx.y * BM;
    const int bn  = blockIdx.x * BN;

    // A-tile loads: thread t loads 4 rows (t/8 + 32*i), float4 at col (t%8)*4
    const int la_row = tid >> 3;
    const int la_c4  = (tid & 7) * 4;

    int rowbase[4];
    #pragma unroll
    for (int i = 0; i < 4; i++) {
        int m   = bm + la_row + 32 * i;
        int n   = m / (OH * OW);
        int rem = m - n * (OH * OW);
        int oh  = rem / OW;
        int ow  = rem - oh * OW;
        rowbase[i] = ((n * H_IN + oh) * W_IN + ow) * C_IN;
    }

    // B-tile loads: thread t loads 4 rows (t/32 + 8*i), float4 at col (t%32)*4
    const int lb_row = tid >> 5;
    const int lb_col = (tid & 31) * 4;

    // compute assignment: 16x16 threads, rows {ty*4..+3, 64+ty*4..+3}, cols likewise with tx
    const int ty = tid >> 4;
    const int tx = tid & 15;

    float acc[8][8];
    #pragma unroll
    for (int i = 0; i < 8; i++)
        #pragma unroll
        for (int j = 0; j < 8; j++)
            acc[i][j] = 0.0f;

    const int NUM_CHUNKS = K_TOTAL / BK;  // 72
    for (int ck = 0; ck < NUM_CHUNKS; ck++) {
        const int p   = ck >> 3;
        const int ic0 = (ck & 7) * 32;
        const int kh  = p / 3;
        const int kw  = p - kh * 3;
        const int a_off = (kh * W_IN + kw) * C_IN + ic0 + la_c4;

        __syncthreads();

        #pragma unroll
        for (int i = 0; i < 4; i++) {
            float4 v = *reinterpret_cast<const float4*>(x + rowbase[i] + a_off);
            *reinterpret_cast<float4*>(&As[la_row + 32 * i][la_c4]) = v;
        }
        const float* Bg = g_B + (ck * BK) * OC + bn;
        #pragma unroll
        for (int i = 0; i < 4; i++) {
            int r = lb_row + 8 * i;
            float4 v = *reinterpret_cast<const float4*>(Bg + r * OC + lb_col);
            *reinterpret_cast<float4*>(&Bs[r][lb_col]) = v;
        }

        __syncthreads();

        #pragma unroll
        for (int kk = 0; kk < BK; kk++) {
            float a[8], b[8];
            #pragma unroll
            for (int i = 0; i < 4; i++) {
                a[i]     = As[ty * 4 + i][kk];
                a[4 + i] = As[64 + ty * 4 + i][kk];
            }
            float4 b0 = *reinterpret_cast<const float4*>(&Bs[kk][tx * 4]);
            float4 b1 = *reinterpret_cast<const float4*>(&Bs[kk][64 + tx * 4]);
            b[0] = b0.x; b[1] = b0.y; b[2] = b0.z; b[3] = b0.w;
            b[4] = b1.x; b[5] = b1.y; b[6] = b1.z; b[7] = b1.w;

            #pragma unroll
            for (int i = 0; i < 8; i++)
                #pragma unroll
                for (int j = 0; j < 8; j++)
                    acc[i][j] = fmaf(a[i], b[j], acc[i][j]);
        }
    }

    // epilogue: + bias, vectorized stores (out is exactly [m][oc] row-major)
    float4 bv0 = *reinterpret_cast<const float4*>(bias + bn + tx * 4);
    float4 bv1 = *reinterpret_cast<const float4*>(bias + bn + 64 + tx * 4);

    #pragma unroll
    for (int i = 0; i < 8; i++) {
        int m = bm + ((i < 4) ? (ty * 4 + i) : (64 + ty * 4 + (i - 4)));
        float* orow = out + (size_t)m * OC + bn;
        float4 o0, o1;
        o0.x = acc[i][0] + bv0.x;
        o0.y = acc[i][1] + bv0.y;
        o0.z = acc[i][2] + bv0.z;
        o0.w = acc[i][3] + bv0.w;
        o1.x = acc[i][4] + bv1.x;
        o1.y = acc[i][5] + bv1.y;
        o1.z = acc[i][6] + bv1.z;
        o1.w = acc[i][7] + bv1.w;
        *reinterpret_cast<float4*>(orow + tx * 4)      = o0;
        *reinterpret_cast<float4*>(orow + 64 + tx * 4) = o1;
    }
}

extern "C" void kernel_launch(void* const* d_in, const int* in_sizes, int n_in,
                              void* d_out, int out_size) {
    const float* x      = (const float*)d_in[0];
    const float* weight = (const float*)d_in[1];
    const float* bias   = (const float*)d_in[2];
    float*       out    = (float*)d_out;

    prep_weight_kernel<<<K_TOTAL, OC>>>(weight);

    dim3 grid(OC / BN, M_TOTAL / BM);  // (2, 729)
    conv_gemm_kernel<<<grid, 256>>>(x, bias, out);
}

// round 3
// speedup vs baseline: 3.6246x; 3.6246x over previous
#include <cuda_runtime.h>
#include <cstdint>

// ---------------------------------------------------------------- problem dims
constexpr int N_IN  = 32;
constexpr int H_IN  = 56;
constexpr int W_IN  = 56;
constexpr int C_IN  = 256;
constexpr int KH    = 3;
constexpr int KW    = 3;
constexpr int OC    = 256;
constexpr int OH    = 54;
constexpr int OW    = 54;

constexpr int M_TOTAL = N_IN * OH * OW;   // 93312
constexpr int K_TOTAL = KH * KW * C_IN;   // 2304
constexpr float SPARSE_TH = 0.01f;

// ---------------------------------------------------------------- GEMM config
constexpr int BM = 128;
constexpr int BN = 128;
constexpr int BK = 32;
constexpr int NUM_CHUNKS = K_TOTAL / BK;  // 72

// smem layout (floats), double buffered
constexpr int A_STRIDE = 36;              // 128x36: frag-gather banks 4g+t -> conflict-free
constexpr int B_STRIDE = 136;             // 32x136: frag-gather banks 8t+g -> conflict-free
constexpr int A_FLOATS = BM * A_STRIDE;   // 4608
constexpr int B_FLOATS = BK * B_STRIDE;   // 4352
constexpr int OFF_A0 = 0;
constexpr int OFF_A1 = A_FLOATS;
constexpr int OFF_B0 = 2 * A_FLOATS;
constexpr int OFF_B1 = 2 * A_FLOATS + B_FLOATS;
constexpr int SMEM_BYTES = (2 * A_FLOATS + 2 * B_FLOATS) * 4;  // 71680

// Pre-thresholded, tf32-rounded weights, layout [k][o], k = (kh*3+kw)*256 + ic
__device__ float g_Bpack[K_TOTAL * OC];

__device__ __forceinline__ uint32_t f2tf32(float v) {
    uint32_t r;
    asm("cvt.rna.tf32.f32 %0, %1;" : "=r"(r) : "f"(v));
    return r;
}

__device__ __forceinline__ uint32_t smem_u32(const void* p) {
    uint32_t a;
    asm("{ .reg .u64 t; cvta.to.shared.u64 t, %1; cvt.u32.u64 %0, t; }" : "=r"(a) : "l"(p));
    return a;
}

__device__ __forceinline__ void mma_tf32(float* c, const uint32_t* a, const uint32_t* b) {
    asm volatile(
        "mma.sync.aligned.m16n8k8.row.col.f32.tf32.tf32.f32 "
        "{%0,%1,%2,%3}, {%4,%5,%6,%7}, {%8,%9}, {%0,%1,%2,%3};"
        : "+f"(c[0]), "+f"(c[1]), "+f"(c[2]), "+f"(c[3])
        : "r"(a[0]), "r"(a[1]), "r"(a[2]), "r"(a[3]), "r"(b[0]), "r"(b[1]));
}

// ---------------------------------------------------------------- prep kernel
__global__ void prep_weight_kernel(const float* __restrict__ w) {
    int k  = blockIdx.x;          // 0..2303
    int o  = threadIdx.x;         // 0..255
    int p  = k >> 8;              // kh*3+kw
    int ic = k & 255;
    float v = w[o * K_TOTAL + ic * (KH * KW) + p];
    if (fabsf(v) < SPARSE_TH) v = 0.0f;
    g_Bpack[k * OC + o] = __uint_as_float(f2tf32(v));
}

// ---------------------------------------------------------------- main kernel
__global__ __launch_bounds__(256, 2)
void conv_mma_kernel(const float* __restrict__ x,
                     const float* __restrict__ bias,
                     float* __restrict__ out) {
    extern __shared__ float smemf[];

    const int tid    = threadIdx.x;
    const int lane   = tid & 31;
    const int wid    = tid >> 5;
    const int warp_m = wid & 1;       // 0..1 (64 rows each)
    const int warp_n = wid >> 1;      // 0..3 (32 cols each)
    const int g      = lane >> 2;     // groupID
    const int t      = lane & 3;      // threadID_in_group

    const int bm = blockIdx.y * BM;
    const int bn = blockIdx.x * BN;

    // ---- A gmem loader assignment: thread loads float4 at rows (tid>>3)+32i, ic col (tid&7)*4
    const int la_row = tid >> 3;
    const int la_c4  = (tid & 7) * 4;
    int rowbase[4];
    #pragma unroll
    for (int i = 0; i < 4; i++) {
        int m   = bm + la_row + 32 * i;
        int n   = m / (OH * OW);
        int rem = m - n * (OH * OW);
        int oh  = rem / OW;
        int ow  = rem - oh * OW;
        rowbase[i] = ((n * H_IN + oh) * W_IN + ow) * C_IN;
    }

    // ---- B cp.async assignment: 1024 segments of 16B (32 rows x 32 segs)
    // idx = tid + 256*ii : row = idx>>5, seg = idx&31
    const uint32_t smem_base_u32 = smem_u32(smemf);

    auto a_gmem_off = [&](int ck) {
        const int p   = ck >> 3;
        const int ic0 = (ck & 7) * 32;
        const int kh  = p / 3;
        const int kw  = p - kh * 3;
        return (kh * W_IN + kw) * C_IN + ic0 + la_c4;
    };

    auto loadB_async = [&](int ck, int buf) {
        const float* src = g_Bpack + (size_t)(ck * BK) * OC + bn;
        const uint32_t dstb = smem_base_u32 + (buf ? OFF_B1 : OFF_B0) * 4;
        #pragma unroll
        for (int ii = 0; ii < 4; ii++) {
            int idx = tid + 256 * ii;
            int row = idx >> 5;
            int seg = idx & 31;
            const float* s = src + row * OC + seg * 4;
            uint32_t d = dstb + (uint32_t)(row * B_STRIDE + seg * 4) * 4;
            asm volatile("cp.async.cg.shared.global [%0], [%1], 16;"
                         :: "r"(d), "l"(s) : "memory");
        }
    };

    auto storeA = [&](const float4* areg, int buf) {
        float* dst = smemf + (buf ? OFF_A1 : OFF_A0);
        #pragma unroll
        for (int i = 0; i < 4; i++) {
            float4 tv;
            tv.x = __uint_as_float(f2tf32(areg[i].x));
            tv.y = __uint_as_float(f2tf32(areg[i].y));
            tv.z = __uint_as_float(f2tf32(areg[i].z));
            tv.w = __uint_as_float(f2tf32(areg[i].w));
            *reinterpret_cast<float4*>(dst + (la_row + 32 * i) * A_STRIDE + la_c4) = tv;
        }
    };

    // ---- accumulators
    float acc[4][4][4];
    #pragma unroll
    for (int i = 0; i < 4; i++)
        #pragma unroll
        for (int j = 0; j < 4; j++)
            #pragma unroll
            for (int r = 0; r < 4; r++)
                acc[i][j][r] = 0.0f;

    // ---- prologue: chunk 0 into buf 0
    {
        const int aoff = a_gmem_off(0);
        float4 areg[4];
        #pragma unroll
        for (int i = 0; i < 4; i++)
            areg[i] = *reinterpret_cast<const float4*>(x + rowbase[i] + aoff);
        loadB_async(0, 0);
        storeA(areg, 0);
        asm volatile("cp.async.commit_group;" ::: "memory");
        asm volatile("cp.async.wait_group 0;" ::: "memory");
        __syncthreads();
    }

    const int aRow0 = warp_m * 64 + g;     // A fragment base row
    const int bCol0 = warp_n * 32 + g;     // B fragment base col

    for (int ck = 0; ck < NUM_CHUNKS; ck++) {
        const int buf = ck & 1;

        // prefetch next chunk's A into regs + issue B cp.async into other buffer
        float4 areg[4];
        const bool have_next = (ck + 1 < NUM_CHUNKS);
        if (have_next) {
            const int aoff = a_gmem_off(ck + 1);
            #pragma unroll
            for (int i = 0; i < 4; i++)
                areg[i] = *reinterpret_cast<const float4*>(x + rowbase[i] + aoff);
            loadB_async(ck + 1, buf ^ 1);
        }
        asm volatile("cp.async.commit_group;" ::: "memory");

        // ---- compute on current buffer
        const float* A = smemf + (buf ? OFF_A1 : OFF_A0);
        const float* B = smemf + (buf ? OFF_B1 : OFF_B0);
        #pragma unroll
        for (int s = 0; s < 4; s++) {
            uint32_t af[4][4];
            #pragma unroll
            for (int i = 0; i < 4; i++) {
                const float* ap = A + (aRow0 + 16 * i) * A_STRIDE + 8 * s + t;
                af[i][0] = __float_as_uint(ap[0]);              // (g,     t)
                af[i][1] = __float_as_uint(ap[8 * A_STRIDE]);   // (g+8,   t)
                af[i][2] = __float_as_uint(ap[4]);              // (g,   t+4)
                af[i][3] = __float_as_uint(ap[8 * A_STRIDE + 4]); // (g+8, t+4)
            }
            uint32_t bf[4][2];
            #pragma unroll
            for (int j = 0; j < 4; j++) {
                const float* bp = B + (8 * s + t) * B_STRIDE + bCol0 + 8 * j;
                bf[j][0] = __float_as_uint(bp[0]);              // (t,   g)
                bf[j][1] = __float_as_uint(bp[4 * B_STRIDE]);   // (t+4, g)
            }
            #pragma unroll
            for (int i = 0; i < 4; i++)
                #pragma unroll
                for (int j = 0; j < 4; j++)
                    mma_tf32(acc[i][j], af[i], bf[j]);
        }

        // ---- store prefetched A into other buffer, then flip
        if (have_next) storeA(areg, buf ^ 1);
        asm volatile("cp.async.wait_group 0;" ::: "memory");
        __syncthreads();
    }

    // ---- epilogue: registers -> gmem with bias
    #pragma unroll
    for (int j = 0; j < 4; j++) {
        const int n = bn + warp_n * 32 + j * 8 + t * 2;
        const float bvx = __ldg(bias + n);
        const float bvy = __ldg(bias + n + 1);
        #pragma unroll
        for (int i = 0; i < 4; i++) {
            const int m = bm + warp_m * 64 + i * 16 + g;
            float2 v0, v1;
            v0.x = acc[i][j][0] + bvx;   // (g,   2t)
            v0.y = acc[i][j][1] + bvy;   // (g,   2t+1)
            v1.x = acc[i][j][2] + bvx;   // (g+8, 2t)
            v1.y = acc[i][j][3] + bvy;   // (g+8, 2t+1)
            *reinterpret_cast<float2*>(out + (size_t)m * OC + n)       = v0;
            *reinterpret_cast<float2*>(out + (size_t)(m + 8) * OC + n) = v1;
        }
    }
}

// ---------------------------------------------------------------- launch
extern "C" void kernel_launch(void* const* d_in, const int* in_sizes, int n_in,
                              void* d_out, int out_size) {
    const float* x      = (const float*)d_in[0];
    const float* weight = (const float*)d_in[1];
    const float* bias   = (const float*)d_in[2];
    float*       out    = (float*)d_out;

    static bool attr_set = false;
    if (!attr_set) {
        cudaFuncSetAttribute(conv_mma_kernel,
                             cudaFuncAttributeMaxDynamicSharedMemorySize, SMEM_BYTES);
        attr_set = true;
    }

    prep_weight_kernel<<<K_TOTAL, OC>>>(weight);

    dim3 grid(OC / BN, M_TOTAL / BM);  // (2, 729)
    conv_mma_kernel<<<grid, 256, SMEM_BYTES>>>(x, bias, out);
}

// round 4
// speedup vs baseline: 7.3256x; 2.0211x over previous
#include <cuda_runtime.h>
#include <cuda_fp16.h>
#include <cstdint>

// ---------------------------------------------------------------- problem dims
constexpr int N_IN  = 32;
constexpr int H_IN  = 56;
constexpr int W_IN  = 56;
constexpr int C_IN  = 256;
constexpr int KH    = 3;
constexpr int KW    = 3;
constexpr int OC    = 256;
constexpr int OH    = 54;
constexpr int OW    = 54;

constexpr int M_TOTAL = N_IN * OH * OW;   // 93312
constexpr int K_TOTAL = KH * KW * C_IN;   // 2304
constexpr float SPARSE_TH = 0.01f;

// ---------------------------------------------------------------- GEMM config
constexpr int BM = 128;
constexpr int BN = 128;
constexpr int BK = 64;                       // 64 fp16 = 128B/row (SW128)
constexpr int NUM_CHUNKS = K_TOTAL / BK;     // 36
constexpr int X_ELEMS = N_IN * H_IN * W_IN * C_IN;  // 25690112

// smem: A chunk 128x64 fp16 = 16KB, B chunk (fragment-packed) 16KB, double buffered
constexpr int A_CHUNK_BYTES = 16384;
constexpr int B_CHUNK_BYTES = 16384;
constexpr int SMEM_BYTES = 2 * (A_CHUNK_BYTES + B_CHUNK_BYTES);  // 65536

// fp16 image of x (prepass output)
__device__ __half g_xh[X_ELEMS];
// B pre-packed in mma fragment order:
// [ck][ntile 0..31][h 0..1][lane 0..31][4 words], word w=(kstep&1)*2+r
// word = half2 { B(k), B(k+1) }, k = ck*64 + kstep*16 + r*8 + t*2, n = ntile*8 + g
__device__ uint32_t g_Bpack[NUM_CHUNKS * 32 * 256];

__device__ __forceinline__ uint32_t smem_u32(const void* p) {
    uint32_t a;
    asm("{ .reg .u64 t; cvta.to.shared.u64 t, %1; cvt.u32.u64 %0, t; }" : "=r"(a) : "l"(p));
    return a;
}

__device__ __forceinline__ void mma_f16(float* c, const uint32_t* a, const uint32_t* b) {
    asm volatile(
        "mma.sync.aligned.m16n8k16.row.col.f32.f16.f16.f32 "
        "{%0,%1,%2,%3}, {%4,%5,%6,%7}, {%8,%9}, {%0,%1,%2,%3};"
        : "+f"(c[0]), "+f"(c[1]), "+f"(c[2]), "+f"(c[3])
        : "r"(a[0]), "r"(a[1]), "r"(a[2]), "r"(a[3]), "r"(b[0]), "r"(b[1]));
}

// ---------------------------------------------------------------- prep: x -> fp16
__global__ void prep_x_kernel(const float* __restrict__ x) {
    int idx = blockIdx.x * 256 + threadIdx.x;       // float4 index
    float4 v = reinterpret_cast<const float4*>(x)[idx];
    __half2 h0 = __floats2half2_rn(v.x, v.y);
    __half2 h1 = __floats2half2_rn(v.z, v.w);
    uint2 u;
    u.x = *reinterpret_cast<uint32_t*>(&h0);
    u.y = *reinterpret_cast<uint32_t*>(&h1);
    reinterpret_cast<uint2*>(g_xh)[idx] = u;
}

// ---------------------------------------------------------------- prep: weights
// threshold + fp16 + pack in exact m16n8k16 B-fragment order
__global__ void prep_B_kernel(const float* __restrict__ w) {
    int blk  = blockIdx.x;           // ck*32 + ntile
    int ck   = blk >> 5;
    int nt   = blk & 31;
    int tid  = threadIdx.x;          // = h*128 + lane*4 + word
    int h    = tid >> 7;
    int lane = (tid >> 2) & 31;
    int wrd  = tid & 3;
    int kstep = h * 2 + (wrd >> 1);
    int r     = wrd & 1;
    int g = lane >> 2, t = lane & 3;
    int n = nt * 8 + g;
    int k = ck * 64 + kstep * 16 + r * 8 + t * 2;
    int p  = k >> 8;                 // tap (kh*3+kw)
    int ic = k & 255;
    float v0 = w[n * K_TOTAL + ic * (KH * KW) + p];
    float v1 = w[n * K_TOTAL + (ic + 1) * (KH * KW) + p];  // k+1 never crosses a tap
    if (fabsf(v0) < SPARSE_TH) v0 = 0.0f;
    if (fabsf(v1) < SPARSE_TH) v1 = 0.0f;
    __half2 hv = __floats2half2_rn(v0, v1);
    g_Bpack[blk * 256 + tid] = *reinterpret_cast<uint32_t*>(&hv);
}

// ---------------------------------------------------------------- main kernel
__global__ __launch_bounds__(256, 2)
void conv_mma_kernel(const float* __restrict__ bias,
                     float* __restrict__ out) {
    extern __shared__ char smem[];
    const uint32_t sb = smem_u32(smem);

    const int tid    = threadIdx.x;
    const int lane   = tid & 31;
    const int wid    = tid >> 5;
    const int warp_m = wid & 1;       // 2 x 64 rows
    const int warp_n = wid >> 1;      // 4 x 32 cols
    const int g      = lane >> 2;
    const int t      = lane & 3;

    const int bm = blockIdx.y * BM;
    const int bn = blockIdx.x * BN;

    // ---- A cp.async assignment: 1024 16B units/chunk, unit = row*8 + u
    const int la_row = tid >> 3;      // 0..31 (+32*i)
    const int la_u   = tid & 7;       // 16B unit within row (8 halves)
    int rowbase[4];
    #pragma unroll
    for (int i = 0; i < 4; i++) {
        int m   = bm + la_row + 32 * i;
        int n   = m / (OH * OW);
        int rem = m - n * (OH * OW);
        int oh  = rem / OW;
        int ow  = rem - oh * OW;
        rowbase[i] = ((n * H_IN + oh) * W_IN + ow) * C_IN;
    }

    auto issue_copies = [&](int ck, int buf) {
        // A: gmem fp16 -> SW128-swizzled smem
        const int p   = ck >> 2;
        const int ic0 = (ck & 3) * 64;
        const int kh  = p / 3;
        const int kw  = p - kh * 3;
        const int aoff = (kh * W_IN + kw) * C_IN + ic0 + la_u * 8;
        const uint32_t aBase = sb + buf * A_CHUNK_BYTES;
        #pragma unroll
        for (int i = 0; i < 4; i++) {
            const __half* src = g_xh + rowbase[i] + aoff;
            uint32_t off = (uint32_t)(la_row + 32 * i) * 128 + la_u * 16;
            off ^= (off >> 3) & 0x70;               // SW128
            asm volatile("cp.async.cg.shared.global [%0], [%1], 16;"
                         :: "r"(aBase + off), "l"(src) : "memory");
        }
        // B: straight 16KB copy of this CTA's 16 ntiles (already fragment-ordered)
        const uint32_t bBase = sb + 2 * A_CHUNK_BYTES + buf * B_CHUNK_BYTES;
        const uint32_t* src = g_Bpack + (size_t)(ck * 32 + (bn >> 3)) * 256;
        #pragma unroll
        for (int ii = 0; ii < 4; ii++) {
            int idx = tid + 256 * ii;               // 16B unit
            asm volatile("cp.async.cg.shared.global [%0], [%1], 16;"
                         :: "r"(bBase + idx * 16), "l"(src + idx * 4) : "memory");
        }
    };

    // ---- accumulators
    float acc[4][4][4];
    #pragma unroll
    for (int i = 0; i < 4; i++)
        #pragma unroll
        for (int j = 0; j < 4; j++)
            #pragma unroll
            for (int r = 0; r < 4; r++)
                acc[i][j][r] = 0.0f;

    // ---- prologue: chunk 0 -> buf 0
    issue_copies(0, 0);
    asm volatile("cp.async.commit_group;" ::: "memory");

    for (int ck = 0; ck < NUM_CHUNKS; ck++) {
        const int buf = ck & 1;

        // barrier for WAR: all warps done computing on buf before its next overwrite
        __syncthreads();

        if (ck + 1 < NUM_CHUNKS) {
            issue_copies(ck + 1, buf ^ 1);
            asm volatile("cp.async.commit_group;" ::: "memory");
            asm volatile("cp.async.wait_group 1;" ::: "memory");   // chunk ck landed
        } else {
            asm volatile("cp.async.wait_group 0;" ::: "memory");
        }
        __syncthreads();

        // ---- compute chunk ck
        const uint32_t aBase = sb + buf * A_CHUNK_BYTES;
        const uint32_t bBase = sb + 2 * A_CHUNK_BYTES + buf * B_CHUNK_BYTES;

        #pragma unroll
        for (int s = 0; s < 4; s++) {              // 4 k-steps of 16
            uint32_t af[4][4];
            #pragma unroll
            for (int i = 0; i < 4; i++) {
                uint32_t off = (uint32_t)(warp_m * 64 + i * 16 + (lane & 15)) * 128
                             + s * 32 + (lane >> 4) * 16;
                off ^= (off >> 3) & 0x70;
                asm volatile(
                    "ldmatrix.sync.aligned.m8n8.x4.shared.b16 {%0,%1,%2,%3}, [%4];"
                    : "=r"(af[i][0]), "=r"(af[i][1]), "=r"(af[i][2]), "=r"(af[i][3])
                    : "r"(aBase + off));
            }
            #pragma unroll
            for (int j = 0; j < 4; j++) {
                const int lt = warp_n * 4 + j;
                uint32_t bf[2];
                asm volatile("ld.shared.v2.b32 {%0,%1}, [%2];"
                             : "=r"(bf[0]), "=r"(bf[1])
                             : "r"(bBase + lt * 1024 + (s >> 1) * 512 + lane * 16 + (s & 1) * 8));
                #pragma unroll
                for (int i = 0; i < 4; i++)
                    mma_f16(acc[i][j], af[i], bf);
            }
        }
    }

    // ---- epilogue: registers -> gmem with bias
    #pragma unroll
    for (int j = 0; j < 4; j++) {
        const int n = bn + warp_n * 32 + j * 8 + t * 2;
        const float bvx = __ldg(bias + n);
        const float bvy = __ldg(bias + n + 1);
        #pragma unroll
        for (int i = 0; i < 4; i++) {
            const int m = bm + warp_m * 64 + i * 16 + g;
            float2 v0, v1;
            v0.x = acc[i][j][0] + bvx;
            v0.y = acc[i][j][1] + bvy;
            v1.x = acc[i][j][2] + bvx;
            v1.y = acc[i][j][3] + bvy;
            *reinterpret_cast<float2*>(out + (size_t)m * OC + n)       = v0;
            *reinterpret_cast<float2*>(out + (size_t)(m + 8) * OC + n) = v1;
        }
    }
}

// ---------------------------------------------------------------- launch
extern "C" void kernel_launch(void* const* d_in, const int* in_sizes, int n_in,
                              void* d_out, int out_size) {
    const float* x      = (const float*)d_in[0];
    const float* weight = (const float*)d_in[1];
    const float* bias   = (const float*)d_in[2];
    float*       out    = (float*)d_out;

    static bool attr_set = false;
    if (!attr_set) {
        cudaFuncSetAttribute(conv_mma_kernel,
                             cudaFuncAttributeMaxDynamicSharedMemorySize, SMEM_BYTES);
        attr_set = true;
    }

    prep_x_kernel<<<X_ELEMS / 4 / 256, 256>>>(x);        // 25088 blocks, exact
    prep_B_kernel<<<NUM_CHUNKS * 32, 256>>>(weight);

    dim3 grid(OC / BN, M_TOTAL / BM);  // (2, 729)
    conv_mma_kernel<<<grid, 256, SMEM_BYTES>>>(bias, out);
}